// round 8
// baseline (speedup 1.0000x reference)
#include <cuda_runtime.h>
#include <math.h>
#include <stdint.h>

// ---------------- problem dims ----------------
#define TT 128
#define NN 1024
#define HH 512
#define II 64
#define G3 1536
#define NSTRIP 16
#define NKSTG 16
#define NTH 512

// ---------------- device scratch ----------------
// weights: [strip][kstage][96 rows][32 k]; rows grouped (hcolgrp*24 + gate*8 + e),
// k XOR-swizzled by 8*(row&3)
__device__ float g_Whh2[NSTRIP * NKSTG * 96 * 32];
__device__ float g_Wih_t[G3 * II];
__device__ float g_hA2[2][NKSTG * NN * 32];           // tf32 h ping-pong
__device__ float g_Gi[(size_t)TT * NSTRIP * NN * 96]; // [t][strip][n][96 cr-order]
__device__ unsigned g_flag[8][16];                    // per (rowblock, strip) progress

// ---------------- helpers ----------------
__device__ __forceinline__ uint32_t f2tf32(float f) {
    uint32_t r;
    asm("cvt.rna.tf32.f32 %0, %1;" : "=r"(r) : "f"(f));
    return r;
}
__device__ __forceinline__ uint32_t smem_u32(const void* p) {
    uint32_t a;
    asm("{ .reg .u64 t; cvta.to.shared.u64 t, %1; cvt.u32.u64 %0, t; }" : "=r"(a) : "l"(p));
    return a;
}
__device__ __forceinline__ float sigf(float x) { return 1.0f / (1.0f + __expf(-x)); }

#define MBARRIER_INIT(addr, cnt) \
    asm volatile("mbarrier.init.shared.b64 [%0], %1;" :: "r"(addr), "r"(cnt) : "memory")
#define MBARRIER_ARRIVE(addr) \
    asm volatile("mbarrier.arrive.shared.b64 _, [%0];" :: "r"(addr) : "memory")
#define MBARRIER_EXPECT_TX(addr, tx) \
    asm volatile("mbarrier.arrive.expect_tx.shared.b64 _, [%0], %1;" \
                 :: "r"(addr), "r"(tx) : "memory")
#define MBARRIER_WAIT_PARITY(mbar_addr, phase_parity) do {                                 \
    uint32_t _mbar = (uint32_t)(mbar_addr);                                                \
    uint32_t _parity = (uint32_t)(phase_parity);                                           \
    uint32_t _done;                                                                        \
    asm volatile(                                                                          \
        "{\n\t.reg .pred p;\n\t"                                                           \
        "mbarrier.try_wait.parity.acquire.cta.shared::cta.b64 p, [%1], %2;\n\t"            \
        "selp.b32 %0, 1, 0, p;\n\t}"                                                       \
        : "=r"(_done) : "r"(_mbar), "r"(_parity) : "memory");                              \
    if (!_done) {                                                                          \
        asm volatile(                                                                      \
            "{\n\t.reg .pred P1;\n\t"                                                      \
            "WAIT_LOOP_%=:\n\t"                                                            \
            "mbarrier.try_wait.parity.acquire.cta.shared::cta.b64 P1, [%0], %1, 0x989680;\n\t" \
            "@P1 bra.uni WAIT_DONE_%=;\n\t"                                                \
            "bra.uni WAIT_LOOP_%=;\n\t"                                                    \
            "WAIT_DONE_%=:\n\t}"                                                           \
            :: "r"(_mbar), "r"(_parity) : "memory");                                       \
    }                                                                                      \
} while (0)

#define BULK_G2S(dst_smem, src_gmem, bytes, mbar) \
    asm volatile("cp.async.bulk.shared::cluster.global.mbarrier::complete_tx::bytes " \
                 "[%0], [%1], %2, [%3];" \
                 :: "r"(dst_smem), "l"(src_gmem), "r"(bytes), "r"(mbar) : "memory")

__device__ __forceinline__ void mma_tf32(float (&c)[4], const uint32_t (&a)[4],
                                         const uint32_t (&b)[2]) {
    asm volatile(
        "mma.sync.aligned.m16n8k8.row.col.f32.tf32.tf32.f32 "
        "{%0,%1,%2,%3}, {%4,%5,%6,%7}, {%8,%9}, {%0,%1,%2,%3};"
        : "+f"(c[0]), "+f"(c[1]), "+f"(c[2]), "+f"(c[3])
        : "r"(a[0]), "r"(a[1]), "r"(a[2]), "r"(a[3]), "r"(b[0]), "r"(b[1]));
}

// ================= prep =================
__global__ void prep_kernel(const float* __restrict__ W_hh,
                            const float* __restrict__ W_ih,
                            const float* __restrict__ hxs) {
    int idx = blockIdx.x * blockDim.x + threadIdx.x;
    if (idx < 128) ((unsigned*)g_flag)[idx] = 0;
    if (idx < G3 * HH) {
        int r = idx >> 9, k = idx & 511;
        int gg = r >> 9, u = r & 511, s = u >> 5, c = u & 31;
        int cr = (c >> 3) * 24 + gg * 8 + (c & 7);
        int kst = k >> 5, kk = k & 31;
        g_Whh2[((s * NKSTG + kst) * 96 + cr) * 32 + (kk ^ (8 * (cr & 3)))] =
            __uint_as_float(f2tf32(W_hh[idx]));
    }
    if (idx < G3 * II) g_Wih_t[idx] = __uint_as_float(f2tf32(W_ih[idx]));
    if (idx < NN * HH) {
        int n = idx >> 9, k = idx & 511;
        int kst = k >> 5, kk = k & 31;
        g_hA2[0][(kst * NN + n) * 32 + (kk ^ (8 * (n & 3)))] =
            __uint_as_float(f2tf32(hxs[idx]));
    }
}

// ================= Gi precompute =================
#define GI_SST 68
__global__ __launch_bounds__(256, 1)
void gi_kernel(const float* __restrict__ X) {
    extern __shared__ float sm[];
    float* Xs = sm;
    float* Ws = sm + 128 * GI_SST;
    const int tid = threadIdx.x;
    const int rb = blockIdx.y * 128;
    const int cb = blockIdx.x * 128;

    #pragma unroll
    for (int it = 0; it < 8; it++) {
        int id = it * 256 + tid;
        int row = id >> 4, c4 = (id & 15) * 4;
        float4 v = *reinterpret_cast<const float4*>(X + (size_t)(rb + row) * II + c4);
        uint4 o = make_uint4(f2tf32(v.x), f2tf32(v.y), f2tf32(v.z), f2tf32(v.w));
        *reinterpret_cast<uint4*>(Xs + row * GI_SST + c4) = o;
        float4 w = *reinterpret_cast<const float4*>(g_Wih_t + (size_t)(cb + row) * II + c4);
        *reinterpret_cast<float4*>(Ws + row * GI_SST + c4) = w;
    }
    __syncthreads();

    const int w = tid >> 5, lane = tid & 31, g = lane >> 2, t = lane & 3;
    const int wr = w & 3, wc = w >> 2;
    float acc[2][8][4];
    #pragma unroll
    for (int sl = 0; sl < 2; sl++)
        #pragma unroll
        for (int j = 0; j < 8; j++)
            #pragma unroll
            for (int q = 0; q < 4; q++) acc[sl][j][q] = 0.0f;

    #pragma unroll
    for (int k8 = 0; k8 < 8; k8++) {
        const int kb = k8 * 8;
        uint32_t a[2][4], b[8][2];
        #pragma unroll
        for (int sl = 0; sl < 2; sl++) {
            int m0 = wr * 32 + sl * 16;
            a[sl][0] = __float_as_uint(Xs[(m0 + g) * GI_SST + kb + t]);
            a[sl][1] = __float_as_uint(Xs[(m0 + 8 + g) * GI_SST + kb + t]);
            a[sl][2] = __float_as_uint(Xs[(m0 + g) * GI_SST + kb + t + 4]);
            a[sl][3] = __float_as_uint(Xs[(m0 + 8 + g) * GI_SST + kb + t + 4]);
        }
        #pragma unroll
        for (int j = 0; j < 8; j++) {
            int n0 = wc * 64 + j * 8;
            b[j][0] = __float_as_uint(Ws[(n0 + g) * GI_SST + kb + t]);
            b[j][1] = __float_as_uint(Ws[(n0 + g) * GI_SST + kb + t + 4]);
        }
        #pragma unroll
        for (int sl = 0; sl < 2; sl++)
            #pragma unroll
            for (int j = 0; j < 8; j++) mma_tf32(acc[sl][j], a[sl], b[j]);
    }

    #pragma unroll
    for (int sl = 0; sl < 2; sl++) {
        #pragma unroll
        for (int j = 0; j < 8; j++) {
            int row = rb + wr * 32 + sl * 16 + g;
            int col = cb + wc * 64 + j * 8 + 2 * t;
            int tt = row >> 10, n = row & 1023;
            int gg = col >> 9, hcol = col & 511, s = hcol >> 5, cl = hcol & 31;
            int cr = (cl >> 3) * 24 + gg * 8 + (cl & 7);
            size_t base0 = (((size_t)tt * NSTRIP + s) * NN + n) * 96 + cr;
            *reinterpret_cast<float2*>(g_Gi + base0) =
                make_float2(acc[sl][j][0], acc[sl][j][1]);
            size_t base1 = (((size_t)tt * NSTRIP + s) * NN + (n + 8)) * 96 + cr;
            *reinterpret_cast<float2*>(g_Gi + base1) =
                make_float2(acc[sl][j][2], acc[sl][j][3]);
        }
    }
}

// ================= persistent GRU kernel =================
#define SW_B   196608                 // resident weights: 16 x 12288
#define A_OFF  196608                 // 2 x 16384 A double buffer
#define SB_OFF 229376                 // bias cache 512 B
#define MB_OFF 229888                 // full0, full1, mbW, empty0, empty1
#define SMEM_STEP 229952

__global__ __launch_bounds__(NTH, 1)
void gru_persist(const float* __restrict__ hxs,
                 const float* __restrict__ masks,
                 const float* __restrict__ b_ih,
                 const float* __restrict__ b_hh,
                 float* __restrict__ out,
                 int has_tail) {
    extern __shared__ char smem[];
    const uint32_t sbase = smem_u32(smem);
    const int tid = threadIdx.x;
    const int strip = blockIdx.x;       // 0..15
    const int rbIdx = blockIdx.y;       // 0..7
    const int rb = rbIdx * 128;

    const uint32_t mbF0 = sbase + MB_OFF;       // full[0]
    const uint32_t mbF1 = mbF0 + 8;             // full[1]
    const uint32_t mbW  = mbF0 + 16;
    const uint32_t mbE0 = mbF0 + 24;            // empty[0]
    const uint32_t mbE1 = mbF0 + 32;            // empty[1]

    const int w = tid >> 5, lane = tid & 31, g = lane >> 2, t2 = (lane & 3) * 2;
    const int wr = w & 7, wc = w >> 3;
    const int r0l = wr * 16 + g;
    const int sw0 = 8 * (g & 3);

    if (tid == 0) {
        MBARRIER_INIT(mbF0, 1);
        MBARRIER_INIT(mbF1, 1);
        MBARRIER_INIT(mbW, 1);
        MBARRIER_INIT(mbE0, NTH);
        MBARRIER_INIT(mbE1, NTH);
    }
    float* sbr  = (float*)(smem + SB_OFF);
    float* sbz  = sbr + 32;
    float* sbni = sbr + 64;
    float* sbnh = sbr + 96;
    if (tid < 32) {
        int gc = strip * 32 + tid;
        sbr[tid]  = b_ih[gc] + b_hh[gc];
        sbz[tid]  = b_ih[512 + gc] + b_hh[512 + gc];
        sbni[tid] = b_ih[1024 + gc];
        sbnh[tid] = b_hh[1024 + gc];
    }
    __syncthreads();

    const float* Wstrip = g_Whh2 + (size_t)strip * NKSTG * 96 * 32;
    if (tid == 0) {
        MBARRIER_EXPECT_TX(mbW, SW_B);
        #pragma unroll
        for (int c4 = 0; c4 < 4; c4++)
            BULK_G2S(sbase + c4 * 49152, Wstrip + c4 * 12288, 49152, mbW);
        // t=0 stages 0,1 from prep-written hA parity 0 (no flags needed)
        MBARRIER_EXPECT_TX(mbF0, 16384);
        BULK_G2S(sbase + A_OFF, &g_hA2[0][(size_t)rb * 32], 16384, mbF0);
        MBARRIER_EXPECT_TX(mbF1, 16384);
        BULK_G2S(sbase + A_OFF + 16384, &g_hA2[0][((size_t)NN + rb) * 32], 16384, mbF1);
    }

    const int R0 = rb + r0l;
    const int R1 = R0 + 8;

    // h leak values carried in registers across steps
    float2 hreg[2][2];
    #pragma unroll
    for (int g3 = 0; g3 < 2; g3++) {
        const int hc = (wc * 2 + g3) * 8 + t2;
        hreg[g3][0] = *reinterpret_cast<const float2*>(&hxs[(size_t)R0 * HH + strip * 32 + hc]);
        hreg[g3][1] = *reinterpret_cast<const float2*>(&hxs[(size_t)R1 * HH + strip * 32 + hc]);
    }

    MBARRIER_WAIT_PARITY(mbW, 0);

    unsigned* myflag = &g_flag[rbIdx][strip];

    for (int t = 0; t < TT; t++) {
        const int par = t & 1;
        const float* hA  = g_hA2[par];
        float*       hAn = g_hA2[par ^ 1];
        const float* Gi_t = g_Gi + ((size_t)t * NSTRIP + strip) * NN * 96;
        const float* mt = masks + (size_t)t * NN;

        // ---- epilogue operand prefetch into registers ----
        const float m0v = mt[R0];
        const float m1v = mt[R1];
        float2 giv[2][3][2];
        #pragma unroll
        for (int g3 = 0; g3 < 2; g3++) {
            const int crb = (wc * 2 + g3) * 24 + t2;
            #pragma unroll
            for (int gate = 0; gate < 3; gate++) {
                giv[g3][gate][0] =
                    *reinterpret_cast<const float2*>(&Gi_t[(size_t)R0 * 96 + crb + gate * 8]);
                giv[g3][gate][1] =
                    *reinterpret_cast<const float2*>(&Gi_t[(size_t)R1 * 96 + crb + gate * 8]);
            }
        }

        float acc[6][4];
        #pragma unroll
        for (int j = 0; j < 6; j++)
            #pragma unroll
            for (int q = 0; q < 4; q++) acc[j][q] = 0.0f;

        // ---- mainloop: no __syncthreads; full/empty mbarrier pipeline ----
        for (int s = 0; s < NKSTG; s++) {
            const uint32_t mbF = (s & 1) ? mbF1 : mbF0;
            const uint32_t mbE = (s & 1) ? mbE1 : mbE0;
            const int ph = (s >> 1) & 1;
            MBARRIER_WAIT_PARITY(mbF, ph);
            const float* As = (const float*)(smem + A_OFF + (s & 1) * 16384);
            const float* Bs = (const float*)(smem + s * 12288);
            #pragma unroll
            for (int k8 = 0; k8 < 4; k8++) {
                const int koff = (k8 * 8 + t2) ^ sw0;
                float2 a0 = *reinterpret_cast<const float2*>(&As[r0l * 32 + koff]);
                float2 a1 = *reinterpret_cast<const float2*>(&As[(r0l + 8) * 32 + koff]);
                uint32_t a[4] = {__float_as_uint(a0.x), __float_as_uint(a1.x),
                                 __float_as_uint(a0.y), __float_as_uint(a1.y)};
                #pragma unroll
                for (int j = 0; j < 6; j++) {
                    int cr = wc * 48 + j * 8 + g;
                    float2 bv = *reinterpret_cast<const float2*>(&Bs[cr * 32 + koff]);
                    uint32_t b[2] = {__float_as_uint(bv.x), __float_as_uint(bv.y)};
                    mma_tf32(acc[j], a, b);
                }
            }
            MBARRIER_ARRIVE(mbE);
            if (tid == 0 && s <= NKSTG - 3) {
                MBARRIER_WAIT_PARITY(mbE, ph);   // buffer fully consumed
                if (t > 0) {
                    unsigned v;
                    do {
                        asm volatile("ld.global.acquire.gpu.u32 %0, [%1];"
                                     : "=r"(v) : "l"(&g_flag[rbIdx][s + 2]) : "memory");
                    } while (v < (unsigned)t);
                    asm volatile("fence.proxy.async;" ::: "memory");
                }
                MBARRIER_EXPECT_TX(mbF, 16384);
                BULK_G2S(sbase + A_OFF + (s & 1) * 16384,
                         hA + ((size_t)(s + 2) * NN + rb) * 32, 16384, mbF);
            }
        }

        // ---- epilogue: gates straight from fragments ----
        float* outT = out + (size_t)t * NN * HH;
        #pragma unroll
        for (int g3 = 0; g3 < 2; g3++) {
            const int jb = g3 * 3;
            const int hc = (wc * 2 + g3) * 8 + t2;
            const int gcol = strip * 32 + hc;
            #pragma unroll
            for (int rs = 0; rs < 2; rs++) {
                const int row = rs ? R1 : R0;
                const float m = rs ? m1v : m0v;
                const float sr0 = acc[jb + 0][rs * 2], sr1 = acc[jb + 0][rs * 2 + 1];
                const float sz0 = acc[jb + 1][rs * 2], sz1 = acc[jb + 1][rs * 2 + 1];
                const float sn0 = acc[jb + 2][rs * 2], sn1 = acc[jb + 2][rs * 2 + 1];
                const float2 gr = giv[g3][0][rs];
                const float2 gz = giv[g3][1][rs];
                const float2 gn = giv[g3][2][rs];
                const float2 hpq = hreg[g3][rs];

                float rv0 = sigf(fmaf(m, sr0 + gr.x, sbr[hc]));
                float rv1 = sigf(fmaf(m, sr1 + gr.y, sbr[hc + 1]));
                float zv0 = sigf(fmaf(m, sz0 + gz.x, sbz[hc]));
                float zv1 = sigf(fmaf(m, sz1 + gz.y, sbz[hc + 1]));
                float nv0 = tanhf(fmaf(m, gn.x, sbni[hc]) + rv0 * fmaf(m, sn0, sbnh[hc]));
                float nv1 = tanhf(fmaf(m, gn.y, sbni[hc + 1]) +
                                  rv1 * fmaf(m, sn1, sbnh[hc + 1]));
                float h0 = fmaf(zv0, fmaf(m, hpq.x, -nv0), nv0);
                float h1 = fmaf(zv1, fmaf(m, hpq.y, -nv1), nv1);
                hreg[g3][rs] = make_float2(h0, h1);

                *reinterpret_cast<float2*>(&outT[(size_t)row * HH + gcol]) =
                    make_float2(h0, h1);
                if (has_tail && t == TT - 1)
                    *reinterpret_cast<float2*>(
                        &out[(size_t)TT * NN * HH + (size_t)row * HH + gcol]) =
                        make_float2(h0, h1);
                uint2 oc = make_uint2(f2tf32(h0), f2tf32(h1));
                *reinterpret_cast<uint2*>(
                    &hAn[((size_t)strip * NN + row) * 32 + (hc ^ (8 * (row & 3)))]) = oc;
            }
        }

        // ---- publish progress; issue next step's stages 0,1 ----
        __threadfence();
        __syncthreads();
        if (tid == 0) {
            asm volatile("st.global.release.gpu.u32 [%0], %1;"
                         :: "l"(myflag), "r"((unsigned)(t + 1)) : "memory");
            if (t + 1 < TT) {
                #pragma unroll
                for (int i = 0; i < 2; i++) {
                    MBARRIER_WAIT_PARITY(i ? mbE1 : mbE0, 1);  // last in-step use parity
                    unsigned v;
                    do {
                        asm volatile("ld.global.acquire.gpu.u32 %0, [%1];"
                                     : "=r"(v) : "l"(&g_flag[rbIdx][i]) : "memory");
                    } while (v < (unsigned)(t + 1));
                    asm volatile("fence.proxy.async;" ::: "memory");
                    MBARRIER_EXPECT_TX(i ? mbF1 : mbF0, 16384);
                    BULK_G2S(sbase + A_OFF + i * 16384,
                             hAn + ((size_t)i * NN + rb) * 32, 16384, i ? mbF1 : mbF0);
                }
            }
        }
    }
}

// ---------------- host ----------------
extern "C" void kernel_launch(void* const* d_in, const int* in_sizes, int n_in,
                              void* d_out, int out_size) {
    const float* hxs   = (const float*)d_in[0];
    const float* masks = (const float*)d_in[2];
    const float* pact  = (const float*)d_in[3];
    const float* W_ih  = (const float*)d_in[4];
    const float* W_hh  = (const float*)d_in[5];
    const float* b_ih  = (const float*)d_in[6];
    const float* b_hh  = (const float*)d_in[7];
    float* out = (float*)d_out;

    static bool attr_set = false;
    if (!attr_set) {
        cudaFuncSetAttribute(gi_kernel, cudaFuncAttributeMaxDynamicSharedMemorySize,
                             2 * 128 * GI_SST * 4);
        cudaFuncSetAttribute(gru_persist, cudaFuncAttributeMaxDynamicSharedMemorySize,
                             SMEM_STEP);
        attr_set = true;
    }

    // 1) prep (also resets progress flags)
    prep_kernel<<<(G3 * HH + 255) / 256, 256>>>(W_hh, W_ih, hxs);

    // 2) Gi precompute
    {
        dim3 grid(G3 / 128, (TT * NN) / 128);
        gi_kernel<<<grid, 256, 2 * 128 * GI_SST * 4>>>(pact);
    }

    // 3) persistent kernel
    const size_t stepElems = (size_t)NN * HH;
    const int has_tail =
        ((size_t)out_size >= (size_t)TT * stepElems + stepElems) ? 1 : 0;
    dim3 grid(NSTRIP, NN / 128);                 // (16, 8) = 128 CTAs, 1/SM
    gru_persist<<<grid, NTH, SMEM_STEP>>>(hxs, masks, b_ih, b_hh, out, has_tail);
}

// round 9
// speedup vs baseline: 1.5388x; 1.5388x over previous
#include <cuda_runtime.h>
#include <math.h>
#include <stdint.h>

// ---------------- problem dims ----------------
#define TT 128
#define NN 1024
#define HH 512
#define II 64
#define G3 1536

// step-kernel tiling: grid (16 strips x 16 rowblocks), CTA tile = 64 rows x 32 hcols
#define NSTRIP 16
#define NKSTG 16
#define NTH 256

// ---------------- device scratch ----------------
// weights: [strip][kstage][96 gate-rows][32 k]  (k XOR-swizzled by 8*(row&3))
__device__ float g_Whh2[NSTRIP * NKSTG * 96 * 32];
__device__ float g_Wih_t[G3 * II];
__device__ float g_hA2[2][NKSTG * NN * 32];
__device__ float g_Gi[(size_t)TT * NSTRIP * NN * 96];

// ---------------- helpers ----------------
__device__ __forceinline__ uint32_t f2tf32(float f) {
    uint32_t r;
    asm("cvt.rna.tf32.f32 %0, %1;" : "=r"(r) : "f"(f));
    return r;
}
__device__ __forceinline__ uint32_t smem_u32(const void* p) {
    uint32_t a;
    asm("{ .reg .u64 t; cvta.to.shared.u64 t, %1; cvt.u32.u64 %0, t; }" : "=r"(a) : "l"(p));
    return a;
}
__device__ __forceinline__ float sigf(float x) { return 1.0f / (1.0f + __expf(-x)); }

#define CP_ASYNC16(dst, src) \
    asm volatile("cp.async.cg.shared.global [%0], [%1], 16;" :: "r"(dst), "l"(src))
#define CP_COMMIT() asm volatile("cp.async.commit_group;" ::: "memory")

#define MBARRIER_INIT(addr, cnt) \
    asm volatile("mbarrier.init.shared.b64 [%0], %1;" :: "r"(addr), "r"(cnt) : "memory")
#define MBARRIER_EXPECT_TX(addr, tx) \
    asm volatile("mbarrier.arrive.expect_tx.shared.b64 _, [%0], %1;" \
                 :: "r"(addr), "r"(tx) : "memory")
#define MBARRIER_WAIT_PARITY(mbar_addr, phase_parity) do {                                 \
    uint32_t _mbar = (uint32_t)(mbar_addr);                                                \
    uint32_t _parity = (uint32_t)(phase_parity);                                           \
    uint32_t _done;                                                                        \
    asm volatile(                                                                          \
        "{\n\t.reg .pred p;\n\t"                                                           \
        "mbarrier.try_wait.parity.acquire.cta.shared::cta.b64 p, [%1], %2;\n\t"            \
        "selp.b32 %0, 1, 0, p;\n\t}"                                                       \
        : "=r"(_done) : "r"(_mbar), "r"(_parity) : "memory");                              \
    if (!_done) {                                                                          \
        asm volatile(                                                                      \
            "{\n\t.reg .pred P1;\n\t"                                                      \
            "WAIT_LOOP_%=:\n\t"                                                            \
            "mbarrier.try_wait.parity.acquire.cta.shared::cta.b64 P1, [%0], %1, 0x989680;\n\t" \
            "@P1 bra.uni WAIT_DONE_%=;\n\t"                                                \
            "bra.uni WAIT_LOOP_%=;\n\t"                                                    \
            "WAIT_DONE_%=:\n\t}"                                                           \
            :: "r"(_mbar), "r"(_parity) : "memory");                                       \
    }                                                                                      \
} while (0)

#define BULK_G2S(dst_smem, src_gmem, bytes, mbar) \
    asm volatile("cp.async.bulk.shared::cluster.global.mbarrier::complete_tx::bytes " \
                 "[%0], [%1], %2, [%3];" \
                 :: "r"(dst_smem), "l"(src_gmem), "r"(bytes), "r"(mbar) : "memory")

__device__ __forceinline__ void mma_tf32(float (&c)[4], const uint32_t (&a)[4],
                                         const uint32_t (&b)[2]) {
    asm volatile(
        "mma.sync.aligned.m16n8k8.row.col.f32.tf32.tf32.f32 "
        "{%0,%1,%2,%3}, {%4,%5,%6,%7}, {%8,%9}, {%0,%1,%2,%3};"
        : "+f"(c[0]), "+f"(c[1]), "+f"(c[2]), "+f"(c[3])
        : "r"(a[0]), "r"(a[1]), "r"(a[2]), "r"(a[3]), "r"(b[0]), "r"(b[1]));
}

// ================= prep (same as R6) =================
__global__ void prep_kernel(const float* __restrict__ W_hh,
                            const float* __restrict__ W_ih,
                            const float* __restrict__ hxs) {
    int idx = blockIdx.x * blockDim.x + threadIdx.x;
    if (idx < G3 * HH) {
        int r = idx >> 9, k = idx & 511;
        int gg = r >> 9, u = r & 511, s = u >> 5, c = u & 31;
        int cr = gg * 32 + c;
        int kst = k >> 5, kk = k & 31;
        g_Whh2[((s * NKSTG + kst) * 96 + cr) * 32 + (kk ^ (8 * (cr & 3)))] =
            __uint_as_float(f2tf32(W_hh[idx]));
    }
    if (idx < G3 * II) g_Wih_t[idx] = __uint_as_float(f2tf32(W_ih[idx]));
    if (idx < NN * HH) {
        int n = idx >> 9, k = idx & 511;
        int kst = k >> 5, kk = k & 31;
        g_hA2[0][(kst * NN + n) * 32 + (kk ^ (8 * (n & 3)))] =
            __uint_as_float(f2tf32(hxs[idx]));
    }
}

// ================= Gi precompute (same as R6) =================
#define GI_SST 68
__global__ __launch_bounds__(256, 1)
void gi_kernel(const float* __restrict__ X) {
    extern __shared__ float sm[];
    float* Xs = sm;
    float* Ws = sm + 128 * GI_SST;
    const int tid = threadIdx.x;
    const int rb = blockIdx.y * 128;
    const int cb = blockIdx.x * 128;

    #pragma unroll
    for (int it = 0; it < 8; it++) {
        int id = it * 256 + tid;
        int row = id >> 4, c4 = (id & 15) * 4;
        float4 v = *reinterpret_cast<const float4*>(X + (size_t)(rb + row) * II + c4);
        uint4 o = make_uint4(f2tf32(v.x), f2tf32(v.y), f2tf32(v.z), f2tf32(v.w));
        *reinterpret_cast<uint4*>(Xs + row * GI_SST + c4) = o;
        float4 w = *reinterpret_cast<const float4*>(g_Wih_t + (size_t)(cb + row) * II + c4);
        *reinterpret_cast<float4*>(Ws + row * GI_SST + c4) = w;
    }
    __syncthreads();

    const int w = tid >> 5, lane = tid & 31, g = lane >> 2, t = lane & 3;
    const int wr = w & 3, wc = w >> 2;
    float acc[2][8][4];
    #pragma unroll
    for (int sl = 0; sl < 2; sl++)
        #pragma unroll
        for (int j = 0; j < 8; j++)
            #pragma unroll
            for (int q = 0; q < 4; q++) acc[sl][j][q] = 0.0f;

    #pragma unroll
    for (int k8 = 0; k8 < 8; k8++) {
        const int kb = k8 * 8;
        uint32_t a[2][4], b[8][2];
        #pragma unroll
        for (int sl = 0; sl < 2; sl++) {
            int m0 = wr * 32 + sl * 16;
            a[sl][0] = __float_as_uint(Xs[(m0 + g) * GI_SST + kb + t]);
            a[sl][1] = __float_as_uint(Xs[(m0 + 8 + g) * GI_SST + kb + t]);
            a[sl][2] = __float_as_uint(Xs[(m0 + g) * GI_SST + kb + t + 4]);
            a[sl][3] = __float_as_uint(Xs[(m0 + 8 + g) * GI_SST + kb + t + 4]);
        }
        #pragma unroll
        for (int j = 0; j < 8; j++) {
            int n0 = wc * 64 + j * 8;
            b[j][0] = __float_as_uint(Ws[(n0 + g) * GI_SST + kb + t]);
            b[j][1] = __float_as_uint(Ws[(n0 + g) * GI_SST + kb + t + 4]);
        }
        #pragma unroll
        for (int sl = 0; sl < 2; sl++)
            #pragma unroll
            for (int j = 0; j < 8; j++) mma_tf32(acc[sl][j], a[sl], b[j]);
    }

    #pragma unroll
    for (int sl = 0; sl < 2; sl++) {
        #pragma unroll
        for (int j = 0; j < 8; j++) {
            int row = rb + wr * 32 + sl * 16 + g;
            int col = cb + wc * 64 + j * 8 + 2 * t;
            int tt = row >> 10, n = row & 1023;
            int gg = col >> 9, hcol = col & 511, s = hcol >> 5, cl = hcol & 31;
            size_t base0 = (((size_t)tt * NSTRIP + s) * NN + n) * 96 + gg * 32 + cl;
            *reinterpret_cast<float2*>(g_Gi + base0) =
                make_float2(acc[sl][j][0], acc[sl][j][1]);
            size_t base1 = (((size_t)tt * NSTRIP + s) * NN + (n + 8)) * 96 + gg * 32 + cl;
            *reinterpret_cast<float2*>(g_Gi + base1) =
                make_float2(acc[sl][j][2], acc[sl][j][3]);
        }
    }
}

// ================= per-step kernel: M=64 tile, 2 CTAs/SM =================
#define NBUF 3
#define A_STG_B 8192                   // 64 rows x 32 k x 4
#define B_STG_B 12288                  // 96 rows x 32 k x 4
#define STG_B (A_STG_B + B_STG_B)      // 20480
#define EPI_GI (NBUF * STG_B)          // 61440 : [64][96] f32 = 24576
#define EPI_HP (EPI_GI + 24576)        // [64][32] f32 = 8192
#define EPI_BI (EPI_HP + 8192)         // [96] f32
#define EPI_BH (EPI_BI + 384)
#define EPI_M  (EPI_BH + 384)          // [64] f32
#define MB_OFF (EPI_M + 256)           // mb0..mb2, mbGi
#define SMEM_STEP (MB_OFF + 64)        // ~95.3 KB -> 2 CTAs/SM
#define SST 100

__global__ __launch_bounds__(NTH)
void gru_step(const float* __restrict__ hA,      // [kst][1024][32]
              float* __restrict__ hA_next,
              const float* __restrict__ h_prev,  // fp32 [1024][512]
              const float* __restrict__ m_t,
              const float* __restrict__ Gi_t,    // [strip][1024][96] (this t)
              const float* __restrict__ Whh2,
              const float* __restrict__ b_ih,
              const float* __restrict__ b_hh,
              float* __restrict__ h_out,
              float* __restrict__ h_out2) {
    extern __shared__ char smem[];
    const uint32_t sbase = smem_u32(smem);
    const int tid = threadIdx.x;
    const int strip = blockIdx.x;      // 0..15
    const int rb = blockIdx.y * 64;    // 0..960

    const uint32_t mb = sbase + MB_OFF;       // full[0..2], Gi at +24
    if (tid == 0) {
        #pragma unroll
        for (int i = 0; i < NBUF; i++) MBARRIER_INIT(mb + 8 * i, 1);
        MBARRIER_INIT(mb + 24, 1);
    }
    __syncthreads();

    const float* Bsrc = Whh2 + (size_t)strip * NKSTG * 96 * 32;

    if (tid == 0) {
        #pragma unroll
        for (int s = 0; s < NBUF; s++) {
            MBARRIER_EXPECT_TX(mb + 8 * s, STG_B);
            BULK_G2S(sbase + s * STG_B,
                     hA + ((size_t)s * NN + rb) * 32, A_STG_B, mb + 8 * s);
            BULK_G2S(sbase + s * STG_B + A_STG_B,
                     Bsrc + (size_t)s * 96 * 32, B_STG_B, mb + 8 * s);
        }
        MBARRIER_EXPECT_TX(mb + 24, 24576);
        BULK_G2S(sbase + EPI_GI,
                 Gi_t + ((size_t)strip * NN + rb) * 96, 24576, mb + 24);
    }

    // epilogue small prefetches
    {
        #pragma unroll
        for (int it = 0; it < 2; it++) {       // h_prev 64x32 = 512 float4
            int id = it * NTH + tid;
            int row = id >> 3, q = id & 7;
            CP_ASYNC16(sbase + EPI_HP + (row * 32 + q * 4) * 4,
                       h_prev + (size_t)(rb + row) * HH + strip * 32 + q * 4);
        }
        if (tid < 24) {
            int c4 = tid * 4, gg = c4 >> 5, cl = c4 & 31;
            CP_ASYNC16(sbase + EPI_BI + c4 * 4, b_ih + gg * HH + strip * 32 + cl);
        } else if (tid < 48) {
            int c4 = (tid - 24) * 4, gg = c4 >> 5, cl = c4 & 31;
            CP_ASYNC16(sbase + EPI_BH + c4 * 4, b_hh + gg * HH + strip * 32 + cl);
        } else if (tid < 64) {
            int c4 = (tid - 48) * 4;
            CP_ASYNC16(sbase + EPI_M + c4 * 4, m_t + rb + c4);
        }
        CP_COMMIT();
    }

    const int w = tid >> 5, lane = tid & 31, g = lane >> 2, t2 = (lane & 3) * 2;
    const int wr = w & 3, wc = w >> 2;         // 4 rowgroups x 2 colgroups
    const int r0 = wr * 16 + g;
    const int sw0 = 8 * (g & 3);

    float acc[6][4];
    #pragma unroll
    for (int j = 0; j < 6; j++)
        #pragma unroll
        for (int q = 0; q < 4; q++) acc[j][q] = 0.0f;

    for (int stg = 0; stg < NKSTG; stg++) {
        const int buf = stg % NBUF;
        MBARRIER_WAIT_PARITY(mb + 8 * buf, (stg / NBUF) & 1);
        const float* As = (const float*)(smem + buf * STG_B);
        const float* Bs = (const float*)(smem + buf * STG_B + A_STG_B);
        #pragma unroll
        for (int k8 = 0; k8 < 4; k8++) {
            const int koff = (k8 * 8 + t2) ^ sw0;
            float2 a0 = *reinterpret_cast<const float2*>(&As[r0 * 32 + koff]);
            float2 a1 = *reinterpret_cast<const float2*>(&As[(r0 + 8) * 32 + koff]);
            uint32_t a[4] = {__float_as_uint(a0.x), __float_as_uint(a1.x),
                             __float_as_uint(a0.y), __float_as_uint(a1.y)};
            #pragma unroll
            for (int j = 0; j < 6; j++) {
                int cr = wc * 48 + j * 8 + g;
                float2 bv = *reinterpret_cast<const float2*>(&Bs[cr * 32 + koff]);
                uint32_t b[2] = {__float_as_uint(bv.x), __float_as_uint(bv.y)};
                mma_tf32(acc[j], a, b);
            }
        }
        __syncthreads();
        if (tid == 0 && stg + NBUF < NKSTG) {
            const int s2 = stg + NBUF;
            MBARRIER_EXPECT_TX(mb + 8 * buf, STG_B);
            BULK_G2S(sbase + buf * STG_B,
                     hA + ((size_t)s2 * NN + rb) * 32, A_STG_B, mb + 8 * buf);
            BULK_G2S(sbase + buf * STG_B + A_STG_B,
                     Bsrc + (size_t)s2 * 96 * 32, B_STG_B, mb + 8 * buf);
        }
    }

    // ---- wait epilogue data; stage accs through smem ----
    MBARRIER_WAIT_PARITY(mb + 24, 0);
    asm volatile("cp.async.wait_group 0;" ::: "memory");
    __syncthreads();
    float* Ssh = (float*)smem;       // [64][SST] over pipeline buffers
    #pragma unroll
    for (int j = 0; j < 6; j++) {
        int c0 = wc * 48 + j * 8 + t2;
        *reinterpret_cast<float2*>(&Ssh[r0 * SST + c0]) = make_float2(acc[j][0], acc[j][1]);
        *reinterpret_cast<float2*>(&Ssh[(r0 + 8) * SST + c0]) =
            make_float2(acc[j][2], acc[j][3]);
    }
    __syncthreads();

    // ---- gates + mask + store: thread = 1 row x 8 cols ----
    {
        const float* sGi = (const float*)(smem + EPI_GI);
        const float* sHp = (const float*)(smem + EPI_HP);
        const float* sBi = (const float*)(smem + EPI_BI);
        const float* sBh = (const float*)(smem + EPI_BH);
        const float* sM  = (const float*)(smem + EPI_M);

        const int row_l = tid >> 2;            // 0..63
        const int cl0 = (tid & 3) * 8;
        const int grow = rb + row_l;
        const int gcol0 = strip * 32 + cl0;
        const float m = sM[row_l];
        float* o1 = h_out + (size_t)grow * HH + gcol0;
        float* o2 = h_out2 ? h_out2 + (size_t)grow * HH + gcol0 : nullptr;
        float* oa = hA_next + ((size_t)strip * NN + grow) * 32;
        const int swr = 8 * (row_l & 3);

        #pragma unroll
        for (int q = 0; q < 2; q++) {
            const int c = cl0 + q * 4;
            float4 Sr = *reinterpret_cast<const float4*>(&Ssh[row_l * SST + c]);
            float4 Sz = *reinterpret_cast<const float4*>(&Ssh[row_l * SST + 32 + c]);
            float4 Sn = *reinterpret_cast<const float4*>(&Ssh[row_l * SST + 64 + c]);
            float4 Gr = *reinterpret_cast<const float4*>(&sGi[row_l * 96 + c]);
            float4 Gz = *reinterpret_cast<const float4*>(&sGi[row_l * 96 + 32 + c]);
            float4 Gn = *reinterpret_cast<const float4*>(&sGi[row_l * 96 + 64 + c]);
            float4 bi_r = *reinterpret_cast<const float4*>(&sBi[c]);
            float4 bi_z = *reinterpret_cast<const float4*>(&sBi[32 + c]);
            float4 bi_n = *reinterpret_cast<const float4*>(&sBi[64 + c]);
            float4 bh_r = *reinterpret_cast<const float4*>(&sBh[c]);
            float4 bh_z = *reinterpret_cast<const float4*>(&sBh[32 + c]);
            float4 bh_n = *reinterpret_cast<const float4*>(&sBh[64 + c]);
            float4 hp = *reinterpret_cast<const float4*>(&sHp[row_l * 32 + c]);

            float hv[4];
            const float* sr = &Sr.x; const float* sz = &Sz.x; const float* sn = &Sn.x;
            const float* gr = &Gr.x; const float* gz = &Gz.x; const float* gn = &Gn.x;
            const float* p1 = &bi_r.x; const float* p2 = &bi_z.x; const float* p3 = &bi_n.x;
            const float* p4 = &bh_r.x; const float* p5 = &bh_z.x; const float* p6 = &bh_n.x;
            const float* ph = &hp.x;
            #pragma unroll
            for (int e = 0; e < 4; e++) {
                float r = sigf(fmaf(m, sr[e] + gr[e], p1[e] + p4[e]));
                float z = sigf(fmaf(m, sz[e] + gz[e], p2[e] + p5[e]));
                float n = tanhf(fmaf(m, gn[e], p3[e]) + r * fmaf(m, sn[e], p6[e]));
                hv[e] = fmaf(z, fmaf(m, ph[e], -n), n);
            }
            float4 o = make_float4(hv[0], hv[1], hv[2], hv[3]);
            *reinterpret_cast<float4*>(o1 + q * 4) = o;
            if (o2) *reinterpret_cast<float4*>(o2 + q * 4) = o;
            uint4 oc = make_uint4(f2tf32(hv[0]), f2tf32(hv[1]), f2tf32(hv[2]), f2tf32(hv[3]));
            *reinterpret_cast<uint4*>(oa + (c ^ swr)) = oc;
        }
    }
}

// ---------------- host ----------------
extern "C" void kernel_launch(void* const* d_in, const int* in_sizes, int n_in,
                              void* d_out, int out_size) {
    const float* hxs   = (const float*)d_in[0];
    const float* masks = (const float*)d_in[2];
    const float* pact  = (const float*)d_in[3];
    const float* W_ih  = (const float*)d_in[4];
    const float* W_hh  = (const float*)d_in[5];
    const float* b_ih  = (const float*)d_in[6];
    const float* b_hh  = (const float*)d_in[7];
    float* out = (float*)d_out;

    static bool attr_set = false;
    if (!attr_set) {
        cudaFuncSetAttribute(gi_kernel, cudaFuncAttributeMaxDynamicSharedMemorySize,
                             2 * 128 * GI_SST * 4);
        cudaFuncSetAttribute(gru_step, cudaFuncAttributeMaxDynamicSharedMemorySize,
                             SMEM_STEP);
        attr_set = true;
    }

    static float* hA0 = nullptr;
    static float* gGi = nullptr;
    static float* gW2 = nullptr;
    if (!hA0) cudaGetSymbolAddress((void**)&hA0, g_hA2);
    if (!gGi) cudaGetSymbolAddress((void**)&gGi, g_Gi);
    if (!gW2) cudaGetSymbolAddress((void**)&gW2, g_Whh2);

    // 1) prep
    prep_kernel<<<(G3 * HH + 255) / 256, 256>>>(W_hh, W_ih, hxs);

    // 2) Gi
    {
        dim3 grid(G3 / 128, (TT * NN) / 128);
        gi_kernel<<<grid, 256, 2 * 128 * GI_SST * 4>>>(pact);
    }

    // 3) sequential steps
    const size_t stepElems = (size_t)NN * HH;
    const size_t hASz = (size_t)NKSTG * NN * 32;
    const bool has_tail = (size_t)out_size >= (size_t)TT * stepElems + stepElems;

    dim3 grid(NSTRIP, NN / 64);                  // (16, 16) = 256 CTAs, 2/SM
    for (int tstep = 0; tstep < TT; tstep++) {
        const float* h_prev = (tstep == 0) ? hxs : out + (size_t)(tstep - 1) * stepElems;
        float* h_out  = out + (size_t)tstep * stepElems;
        float* h_out2 = (tstep == TT - 1 && has_tail) ? out + (size_t)TT * stepElems
                                                      : nullptr;
        const float* hA_cur  = hA0 + (size_t)(tstep & 1) * hASz;
        float*       hA_next = hA0 + (size_t)((tstep + 1) & 1) * hASz;
        gru_step<<<grid, NTH, SMEM_STEP>>>(
            hA_cur, hA_next, h_prev,
            masks + (size_t)tstep * NN,
            gGi + (size_t)tstep * NSTRIP * NN * 96,
            gW2, b_ih, b_hh, h_out, h_out2);
    }
}